// round 16
// baseline (speedup 1.0000x reference)
#include <cuda_runtime.h>
#include <cuda_bf16.h>
#include <cstdint>

// upfirdn2d: up=2, down=1, pad=(2,1), 4x4 separable FIR (rank-1: K = g x f).
// Input 2048 planes of 128x128 f32 -> Output 2048 planes of 256x256 f32.
//
// Fully async memory pipeline:
//   reads : per-lane cp.async (LDGSTS, 16B) into a per-warp SMEM ring,
//           depth 3 chunks x 2 rows, consumed 2 chunks behind issue.
//   writes: 4 output rows (4KB contiguous) double-buffered in SMEM,
//           flushed with cp.async.bulk S2G (L2 evict_first policy --
//           output is write-once; preserve L2 for input reuse).
// One warp spans a full input row (32 lanes x float4); halo via shuffles,
// true zero-pad at lanes 0/31. 4 warps x 32 rows = one plane per block.
// smem 44KB -> 5 CTAs/SM (20 warps). Stage loop fully unrolled.

#define H   128
#define W   128
#define OW  256
#define NW  4      // warps per block
#define RPW 32     // input rows per warp
#define NCHUNK (RPW / 2)   // 16 chunks of 2 rows
#define RING 3

__global__ __launch_bounds__(128, 5) void fir_up2_kernel(
    const float* __restrict__ x,
    const float* __restrict__ kern,
    float* __restrict__ out)
{
    __shared__ __align__(16) float inring[NW][RING][2 * W];   // 12KB
    __shared__ __align__(16) float stage[NW][2][4 * OW];      // 32KB

    const int plane = blockIdx.x;
    const int warp  = threadIdx.x >> 5;
    const int lane  = threadIdx.x & 31;
    const int r0    = warp * RPW;          // 4 warps x 32 rows = 128
    const int c0    = lane * 4;            // input col of this lane's float4

    const float* __restrict__ xp = x + (size_t)plane * (H * W);
    float* __restrict__ op = out + (size_t)plane * (OW * 2 * H);

    // taps (rank-1 factorization of the 4x4 kernel)
    const float f0 = __ldg(kern + 4 + 0);
    const float f1 = __ldg(kern + 4 + 1);
    const float f2 = __ldg(kern + 4 + 2);
    const float f3 = __ldg(kern + 4 + 3);
    const float inv = 1.0f / f1;
    const float g0 = __ldg(kern + 0 * 4 + 1) * inv;
    const float g2 = __ldg(kern + 2 * 4 + 1) * inv;
    const float g3 = __ldg(kern + 3 * 4 + 1) * inv;

    // L2 evict-first policy for the write-once output stream.
    uint64_t pol;
    asm volatile("createpolicy.fractional.L2::evict_first.b64 %0, 1.0;" : "=l"(pol));

    // Issue async copy of chunk k (input rows r0+2k+1, r0+2k+2) into ring
    // slot k%RING. Each lane moves only its own 16B per row.
    auto issue_chunk = [&](int k) {
        const int s = k % RING;
#pragma unroll
        for (int j = 0; j < 2; j++) {
            const int r = r0 + 2 * k + 1 + j;
            float* dstp = &inring[warp][s][j * W + c0];
            uint32_t sa = (uint32_t)__cvta_generic_to_shared(dstp);
            if (r < H) {
                const float* src = xp + r * W + c0;
                asm volatile(
                    "cp.async.cg.shared.global [%0], [%1], 16;"
                    :: "r"(sa), "l"(src) : "memory");
            } else {
                *(float4*)dstp = make_float4(0.f, 0.f, 0.f, 0.f);
            }
        }
        asm volatile("cp.async.commit_group;" ::: "memory");
    };

    // Horizontal half-convolution of one raw row -> 8 output-col values.
    auto hconv = [&](float4 v, float h[8]) {
        float m = __shfl_up_sync(0xffffffffu, v.w, 1);
        if (lane == 0) m = 0.0f;               // true left zero-pad
        float q = __shfl_down_sync(0xffffffffu, v.x, 1);
        if (lane == 31) q = 0.0f;              // true right zero-pad
        h[0] = f3 * m   + f1 * v.x;
        h[1] = f2 * v.x + f0 * v.y;
        h[2] = f3 * v.x + f1 * v.y;
        h[3] = f2 * v.y + f0 * v.z;
        h[4] = f3 * v.y + f1 * v.z;
        h[5] = f2 * v.z + f0 * v.w;
        h[6] = f3 * v.z + f1 * v.w;
        h[7] = f2 * v.w + f0 * q;
    };

    // Vertical combine (ha=h(r-1), hb=h(r), hc=h(r+1)) -> SMEM stage rows.
    auto emit_smem = [&](float* sb, int local,
                         const float ha[8], const float hb[8], const float hc[8]) {
        float4 e0, e1, o0, o1;
        e0.x = g3 * ha[0] + hb[0];
        e0.y = g3 * ha[1] + hb[1];
        e0.z = g3 * ha[2] + hb[2];
        e0.w = g3 * ha[3] + hb[3];
        e1.x = g3 * ha[4] + hb[4];
        e1.y = g3 * ha[5] + hb[5];
        e1.z = g3 * ha[6] + hb[6];
        e1.w = g3 * ha[7] + hb[7];
        o0.x = g2 * hb[0] + g0 * hc[0];
        o0.y = g2 * hb[1] + g0 * hc[1];
        o0.z = g2 * hb[2] + g0 * hc[2];
        o0.w = g2 * hb[3] + g0 * hc[3];
        o1.x = g2 * hb[4] + g0 * hc[4];
        o1.y = g2 * hb[5] + g0 * hc[5];
        o1.z = g2 * hb[6] + g0 * hc[6];
        o1.w = g2 * hb[7] + g0 * hc[7];
        const int oc = 8 * lane;
        float* re = sb + (2 * local) * OW + oc;
        float* ro = sb + (2 * local + 1) * OW + oc;
        *(float4*)(re)     = e0;
        *(float4*)(re + 4) = e1;
        *(float4*)(ro)     = o0;
        *(float4*)(ro + 4) = o1;
    };

    // Prologue: halo rows r0-1, r0 via plain LDG (registers);
    // ring chunks 0,1 in flight.
    float hprev[8], hcur[8], hn1[8], hn2[8];
    {
        float4 va = (r0 - 1 >= 0) ? *(const float4*)(xp + (r0 - 1) * W + c0)
                                  : make_float4(0.f, 0.f, 0.f, 0.f);
        float4 vb = *(const float4*)(xp + r0 * W + c0);
        hconv(va, hprev);
        hconv(vb, hcur);
    }
    issue_chunk(0);
    issue_chunk(1);

#pragma unroll
    for (int i = 0; i < NCHUNK; i++) {
        const int r = r0 + 2 * i;
        const int buf = i & 1;

        // Keep the read ring 2 chunks deep (empty commit keeps counts uniform).
        if (i + 2 < NCHUNK) issue_chunk(i + 2);
        else asm volatile("cp.async.commit_group;" ::: "memory");

        // Reuse guard for the output buffer handed to the copy engine 2 stages ago.
        if (i >= 2) {
            if (lane == 0)
                asm volatile("cp.async.bulk.wait_group.read 1;" ::: "memory");
            __syncwarp();
        }

        // Chunk i ready once all but the 2 newest groups have drained.
        asm volatile("cp.async.wait_group 2;" ::: "memory");
        const int s = i % RING;
        float4 v1 = *(const float4*)&inring[warp][s][0 * W + c0];
        float4 v2 = *(const float4*)&inring[warp][s][1 * W + c0];

        hconv(v1, hn1);
        hconv(v2, hn2);

        float* sb = &stage[warp][buf][0];
        emit_smem(sb, 0, hprev, hcur, hn1);   // output rows 2r,   2r+1
        emit_smem(sb, 1, hcur,  hn1,  hn2);   // output rows 2r+2, 2r+3

        // Order STS vs async proxy; elect one lane to fire the 4KB burst.
        asm volatile("fence.proxy.async.shared::cta;" ::: "memory");
        __syncwarp();
        if (lane == 0) {
            uint32_t saddr = (uint32_t)__cvta_generic_to_shared(sb);
            float* gdst = op + (size_t)(2 * r) * OW;
            asm volatile(
                "cp.async.bulk.global.shared::cta.bulk_group.L2::cache_hint "
                "[%0], [%1], %2, %3;"
                :: "l"(gdst), "r"(saddr), "r"(4 * OW * 4), "l"(pol) : "memory");
            asm volatile("cp.async.bulk.commit_group;" ::: "memory");
        }

#pragma unroll
        for (int j = 0; j < 8; j++) { hprev[j] = hn1[j]; hcur[j] = hn2[j]; }
    }

    // Drain all outstanding bulk stores before exit.
    if (lane == 0)
        asm volatile("cp.async.bulk.wait_group 0;" ::: "memory");
}

extern "C" void kernel_launch(void* const* d_in, const int* in_sizes, int n_in,
                              void* d_out, int out_size) {
    const float* x = (const float*)d_in[0];
    const float* k = (const float*)d_in[1];
    float* out = (float*)d_out;

    const int planes = in_sizes[0] / (H * W);   // 2048
    fir_up2_kernel<<<planes, 128>>>(x, k, out);
}

// round 17
// speedup vs baseline: 1.1194x; 1.1194x over previous
#include <cuda_runtime.h>
#include <cuda_bf16.h>
#include <cstdint>

// upfirdn2d: up=2, down=1, pad=(2,1), 4x4 separable FIR (rank-1: K = g x f).
// Input 2048 planes of 128x128 f32 -> Output 2048 planes of 256x256 f32.
//
// Fully async memory pipeline:
//   reads : per-lane cp.async (LDGSTS, 16B) into a per-warp SMEM ring,
//           depth 3 chunks x 2 rows, consumed 2 chunks behind issue
//           (cp.async.wait_group 2) -> 4 rows of read lookahead.
//   writes: 4 output rows (4KB contiguous) double-buffered in SMEM,
//           flushed with cp.async.bulk S2G, L2::evict_first policy
//           (output is write-once -> preserve L2 capacity for input reuse).
// One warp spans a full input row (32 lanes x float4); halo via shuffles,
// true zero-pad at lanes 0/31. 4 warps x 32 rows = one plane per block.
// smem 44KB -> 5 CTAs/SM (20 warps).

#define H   128
#define W   128
#define OW  256
#define NW  4      // warps per block
#define RPW 32     // input rows per warp
#define NCHUNK (RPW / 2)   // 16 chunks of 2 rows
#define RING 3

__global__ __launch_bounds__(128, 5) void fir_up2_kernel(
    const float* __restrict__ x,
    const float* __restrict__ kern,
    float* __restrict__ out)
{
    __shared__ __align__(16) float inring[NW][RING][2 * W];   // 12KB
    __shared__ __align__(16) float stage[NW][2][4 * OW];      // 32KB

    const int plane = blockIdx.x;
    const int warp  = threadIdx.x >> 5;
    const int lane  = threadIdx.x & 31;
    const int r0    = warp * RPW;          // 4 warps x 32 rows = 128
    const int c0    = lane * 4;            // input col of this lane's float4

    const float* __restrict__ xp = x + (size_t)plane * (H * W);
    float* __restrict__ op = out + (size_t)plane * (OW * 2 * H);

    // taps (rank-1 factorization of the 4x4 kernel)
    const float f0 = __ldg(kern + 4 + 0);
    const float f1 = __ldg(kern + 4 + 1);
    const float f2 = __ldg(kern + 4 + 2);
    const float f3 = __ldg(kern + 4 + 3);
    const float inv = 1.0f / f1;
    const float g0 = __ldg(kern + 0 * 4 + 1) * inv;
    const float g2 = __ldg(kern + 2 * 4 + 1) * inv;
    const float g3 = __ldg(kern + 3 * 4 + 1) * inv;

    // L2 evict-first policy for the write-once output stream.
    uint64_t pol;
    asm volatile("createpolicy.fractional.L2::evict_first.b64 %0, 1.0;" : "=l"(pol));

    // Issue async copy of chunk k (input rows r0+2k+1, r0+2k+2) into ring
    // slot k%RING. Each lane moves only its own 16B per row.
    auto issue_chunk = [&](int k) {
        const int s = k % RING;
#pragma unroll
        for (int j = 0; j < 2; j++) {
            const int r = r0 + 2 * k + 1 + j;
            float* dstp = &inring[warp][s][j * W + c0];
            uint32_t sa = (uint32_t)__cvta_generic_to_shared(dstp);
            if (r < H) {
                const float* src = xp + r * W + c0;
                asm volatile(
                    "cp.async.cg.shared.global [%0], [%1], 16;"
                    :: "r"(sa), "l"(src) : "memory");
            } else {
                *(float4*)dstp = make_float4(0.f, 0.f, 0.f, 0.f);
            }
        }
        asm volatile("cp.async.commit_group;" ::: "memory");
    };

    // Horizontal half-convolution of one raw row -> 8 output-col values.
    auto hconv = [&](float4 v, float h[8]) {
        float m = __shfl_up_sync(0xffffffffu, v.w, 1);
        if (lane == 0) m = 0.0f;               // true left zero-pad
        float q = __shfl_down_sync(0xffffffffu, v.x, 1);
        if (lane == 31) q = 0.0f;              // true right zero-pad
        h[0] = f3 * m   + f1 * v.x;
        h[1] = f2 * v.x + f0 * v.y;
        h[2] = f3 * v.x + f1 * v.y;
        h[3] = f2 * v.y + f0 * v.z;
        h[4] = f3 * v.y + f1 * v.z;
        h[5] = f2 * v.z + f0 * v.w;
        h[6] = f3 * v.z + f1 * v.w;
        h[7] = f2 * v.w + f0 * q;
    };

    // Vertical combine (ha=h(r-1), hb=h(r), hc=h(r+1)) -> SMEM stage rows.
    auto emit_smem = [&](float* sb, int local,
                         const float ha[8], const float hb[8], const float hc[8]) {
        float4 e0, e1, o0, o1;
        e0.x = g3 * ha[0] + hb[0];
        e0.y = g3 * ha[1] + hb[1];
        e0.z = g3 * ha[2] + hb[2];
        e0.w = g3 * ha[3] + hb[3];
        e1.x = g3 * ha[4] + hb[4];
        e1.y = g3 * ha[5] + hb[5];
        e1.z = g3 * ha[6] + hb[6];
        e1.w = g3 * ha[7] + hb[7];
        o0.x = g2 * hb[0] + g0 * hc[0];
        o0.y = g2 * hb[1] + g0 * hc[1];
        o0.z = g2 * hb[2] + g0 * hc[2];
        o0.w = g2 * hb[3] + g0 * hc[3];
        o1.x = g2 * hb[4] + g0 * hc[4];
        o1.y = g2 * hb[5] + g0 * hc[5];
        o1.z = g2 * hb[6] + g0 * hc[6];
        o1.w = g2 * hb[7] + g0 * hc[7];
        const int oc = 8 * lane;
        float* re = sb + (2 * local) * OW + oc;
        float* ro = sb + (2 * local + 1) * OW + oc;
        *(float4*)(re)     = e0;
        *(float4*)(re + 4) = e1;
        *(float4*)(ro)     = o0;
        *(float4*)(ro + 4) = o1;
    };

    // Prologue: halo rows r0-1, r0 via plain LDG (registers);
    // ring chunks 0,1 in flight.
    float hprev[8], hcur[8], hn1[8], hn2[8];
    {
        float4 va = (r0 - 1 >= 0) ? *(const float4*)(xp + (r0 - 1) * W + c0)
                                  : make_float4(0.f, 0.f, 0.f, 0.f);
        float4 vb = *(const float4*)(xp + r0 * W + c0);
        hconv(va, hprev);
        hconv(vb, hcur);
    }
    issue_chunk(0);
    issue_chunk(1);

#pragma unroll 2
    for (int i = 0; i < NCHUNK; i++) {
        const int r = r0 + 2 * i;
        const int buf = i & 1;

        // Keep the read ring 2 chunks deep (empty commit keeps counts uniform).
        if (i + 2 < NCHUNK) issue_chunk(i + 2);
        else asm volatile("cp.async.commit_group;" ::: "memory");

        // Reuse guard for the output buffer handed to the copy engine 2 stages ago.
        if (i >= 2) {
            if (lane == 0)
                asm volatile("cp.async.bulk.wait_group.read 1;" ::: "memory");
            __syncwarp();
        }

        // Chunk i ready once all but the 2 newest groups have drained.
        asm volatile("cp.async.wait_group 2;" ::: "memory");
        const int s = i % RING;
        float4 v1 = *(const float4*)&inring[warp][s][0 * W + c0];
        float4 v2 = *(const float4*)&inring[warp][s][1 * W + c0];

        hconv(v1, hn1);
        hconv(v2, hn2);

        float* sb = &stage[warp][buf][0];
        emit_smem(sb, 0, hprev, hcur, hn1);   // output rows 2r,   2r+1
        emit_smem(sb, 1, hcur,  hn1,  hn2);   // output rows 2r+2, 2r+3

        // Order STS vs async proxy; elect one lane to fire the 4KB burst.
        asm volatile("fence.proxy.async.shared::cta;" ::: "memory");
        __syncwarp();
        if (lane == 0) {
            uint32_t saddr = (uint32_t)__cvta_generic_to_shared(sb);
            float* gdst = op + (size_t)(2 * r) * OW;
            asm volatile(
                "cp.async.bulk.global.shared::cta.bulk_group.L2::cache_hint "
                "[%0], [%1], %2, %3;"
                :: "l"(gdst), "r"(saddr), "r"(4 * OW * 4), "l"(pol) : "memory");
            asm volatile("cp.async.bulk.commit_group;" ::: "memory");
        }

#pragma unroll
        for (int j = 0; j < 8; j++) { hprev[j] = hn1[j]; hcur[j] = hn2[j]; }
    }

    // Drain all outstanding bulk stores before exit.
    if (lane == 0)
        asm volatile("cp.async.bulk.wait_group 0;" ::: "memory");
}

extern "C" void kernel_launch(void* const* d_in, const int* in_sizes, int n_in,
                              void* d_out, int out_size) {
    const float* x = (const float*)d_in[0];
    const float* k = (const float*)d_in[1];
    float* out = (float*)d_out;

    const int planes = in_sizes[0] / (H * W);   // 2048
    fir_up2_kernel<<<planes, 128>>>(x, k, out);
}